// round 4
// baseline (speedup 1.0000x reference)
#include <cuda_runtime.h>
#include <cstdint>
#include <cstddef>
#include <float.h>

// ---------------- problem constants ----------------
constexpr int B   = 8;
constexpr int N0  = 8192;
constexpr int CX  = 24;
constexpr int S1  = 1024, K1 = 16;
constexpr int S2  = 512,  K2 = 32;

// ---------------- scratch ----------------
__device__ float g_xt    [B * N0 * CX];
__device__ float g_l0xyz [B * N0 * 3];
__device__ float g_l1xyz [B * S1 * 3];
__device__ int   g_ball1 [B * S1 * K1];
__device__ float g_l1p   [B * S1 * 128];
__device__ float g_l2xyz [B * S2 * 3];
__device__ int   g_ball2 [B * S2 * K2];
__device__ float g_l2p   [B * S2 * 256];
__device__ int   g_nn2i  [B * S1 * 3];
__device__ float g_nn2w  [B * S1 * 3];
__device__ float g_l1p2  [B * S1 * 256];
__device__ int   g_nn1i  [B * N0 * 3];
__device__ float g_nn1w  [B * N0 * 3];
__device__ float g_wt    [378112];

constexpr int OFF_SA1_0 = 0;        // 28 x 64
constexpr int OFF_SA1_1 = 1792;     // 64 x 128
constexpr int OFF_SA1_2 = 9984;     // 128 x 128
constexpr int OFF_SA2_0 = 26368;    // 132 x 128
constexpr int OFF_SA2_1 = 43264;    // 128 x 256
constexpr int OFF_FP2_0 = 76032;    // 384 x 256
constexpr int OFF_FP2_1 = 174336;   // 256 x 256
constexpr int OFF_FP1_0 = 239872;   // 284 x 256
constexpr int OFF_FP1_1 = 312576;   // 256 x 256

// ---------------- f32x2 packed helpers ----------------
using u64 = unsigned long long;
__device__ __forceinline__ u64 pk2(float lo, float hi) {
    u64 r; asm("mov.b64 %0, {%1, %2};" : "=l"(r) : "f"(lo), "f"(hi)); return r;
}
__device__ __forceinline__ float2 up2(u64 v) {
    float lo, hi; asm("mov.b64 {%0, %1}, %2;" : "=f"(lo), "=f"(hi) : "l"(v));
    return make_float2(lo, hi);
}
__device__ __forceinline__ void fma2(u64& d, u64 a, u64 b) {
    asm("fma.rn.f32x2 %0, %1, %2, %0;" : "+l"(d) : "l"(a), "l"(b));
}
__device__ __forceinline__ u64 add2(u64 a, u64 b) {
    u64 r; asm("add.rn.f32x2 %0, %1, %2;" : "=l"(r) : "l"(a), "l"(b)); return r;
}
__device__ __forceinline__ u64 mul2(u64 a, u64 b) {
    u64 r; asm("mul.rn.f32x2 %0, %1, %2;" : "=l"(r) : "l"(a), "l"(b)); return r;
}

// ---------------- numeric helpers (pinned op order) ----------------
__device__ __forceinline__ float sumsq3(float x, float y, float z) {
    return fmaf(z, z, fmaf(y, y, __fmul_rn(x, x)));
}
__device__ __forceinline__ float sqdist_cancel(float sc, float cx, float cy, float cz,
                                               float px, float py, float pz) {
    float sp  = sumsq3(px, py, pz);
    float dot = fmaf(cz, pz, fmaf(cy, py, __fmul_rn(cx, px)));
    return __fsub_rn(__fadd_rn(sc, sp), __fmul_rn(2.0f, dot));
}
__device__ __forceinline__ void top3_insert(float d, int p,
                                            float& D0, float& D1, float& D2,
                                            int& I0, int& I1, int& I2) {
    if (d < D2 || (d == D2 && p < I2)) {
        if (d < D1 || (d == D1 && p < I1)) {
            D2 = D1; I2 = I1;
            if (d < D0 || (d == D0 && p < I0)) { D1 = D0; I1 = I0; D0 = d; I0 = p; }
            else                               { D1 = d;  I1 = p; }
        } else { D2 = d; I2 = p; }
    }
}

// packed GEMM microkernels: acc[r][j] = u64 (even-k partial, odd-k partial)
template <int NR>
__device__ __forceinline__ void mm4p(const float* __restrict__ wt, int O, int og, int KP,
                                     const float* __restrict__ in0, int ld, u64 (&acc)[NR][4]) {
    const float4* wt4 = reinterpret_cast<const float4*>(wt);
    const int OV4 = O >> 2;
#pragma unroll 2
    for (int k = 0; k < KP; k += 4) {
        float4 wa = wt4[(k + 0) * OV4 + og];
        float4 wb = wt4[(k + 1) * OV4 + og];
        float4 wc = wt4[(k + 2) * OV4 + og];
        float4 wd = wt4[(k + 3) * OV4 + og];
        u64 p0x = pk2(wa.x, wb.x), p0y = pk2(wa.y, wb.y), p0z = pk2(wa.z, wb.z), p0w = pk2(wa.w, wb.w);
        u64 p1x = pk2(wc.x, wd.x), p1y = pk2(wc.y, wd.y), p1z = pk2(wc.z, wd.z), p1w = pk2(wc.w, wd.w);
#pragma unroll
        for (int r = 0; r < NR; r++) {
            const ulonglong2 g = *reinterpret_cast<const ulonglong2*>(in0 + r * ld + k);
            fma2(acc[r][0], g.x, p0x); fma2(acc[r][0], g.y, p1x);
            fma2(acc[r][1], g.x, p0y); fma2(acc[r][1], g.y, p1y);
            fma2(acc[r][2], g.x, p0z); fma2(acc[r][2], g.y, p1z);
            fma2(acc[r][3], g.x, p0w); fma2(acc[r][3], g.y, p1w);
        }
    }
}

template <int NR>
__device__ __forceinline__ void mmcolp(const float* __restrict__ wt, int O, int o, int KP,
                                       const float* __restrict__ in0, int ld, u64 (&acc)[NR]) {
#pragma unroll 2
    for (int k = 0; k < KP; k += 4) {
        float wa = wt[(k + 0) * O + o];
        float wb = wt[(k + 1) * O + o];
        float wc = wt[(k + 2) * O + o];
        float wd = wt[(k + 3) * O + o];
        u64 p01 = pk2(wa, wb), p23 = pk2(wc, wd);
#pragma unroll
        for (int r = 0; r < NR; r++) {
            const ulonglong2 g = *reinterpret_cast<const ulonglong2*>(in0 + r * ld + k);
            fma2(acc[r], g.x, p01);
            fma2(acc[r], g.y, p23);
        }
    }
}

// ---------------- prep ----------------
__global__ void transpose_x_kernel(const float* __restrict__ xyz) {
    int i = blockIdx.x * blockDim.x + threadIdx.x;   // over B*CX*N0
    if (i >= B * CX * N0) return;
    int b = i / (CX * N0);
    int rem = i - b * (CX * N0);
    int c = rem / N0;
    int n = rem - c * N0;
    float v = xyz[i];
    g_xt[((size_t)b * N0 + n) * CX + c] = v;
    if (c < 3) g_l0xyz[((size_t)b * N0 + n) * 3 + c] = v;
}

struct WT9 {
    const float* W[9];
    int off[9], O[9], K[9], Kpad[9];
};
__global__ void transpose_w9_kernel(WT9 w) {
    int i = blockIdx.x * blockDim.x + threadIdx.x;
#pragma unroll
    for (int s = 0; s < 9; s++) {
        int n = w.Kpad[s] * w.O[s];
        if (i < n) {
            int k = i / w.O[s], o = i - k * w.O[s];
            g_wt[w.off[s] + i] = (k < w.K[s]) ? w.W[s][o * w.K[s] + k] : 0.0f;
            return;
        }
        i -= n;
    }
}

// ---------------- FPS (8 pts/thread, packed f32x2 distance math) ----------------
__global__ void __launch_bounds__(1024) fps8_kernel(const float* __restrict__ pts,
                                                    float* __restrict__ outxyz) {
    int b = blockIdx.x, tid = threadIdx.x;
    const float* base = pts + (size_t)b * N0 * 3;
    u64 px2[4], py2[4], pz2[4];
    float dist[8];
#pragma unroll
    for (int h = 0; h < 4; h++) {
        int p0 = tid + (2 * h) * 1024, p1 = tid + (2 * h + 1) * 1024;
        px2[h] = pk2(base[p0 * 3 + 0], base[p1 * 3 + 0]);
        py2[h] = pk2(base[p0 * 3 + 1], base[p1 * 3 + 1]);
        pz2[h] = pk2(base[p0 * 3 + 2], base[p1 * 3 + 2]);
    }
#pragma unroll
    for (int j = 0; j < 8; j++) dist[j] = 1e10f;
    __shared__ int   s_far;
    __shared__ float s_v[32];
    __shared__ int   s_i[32];
    if (tid == 0) s_far = 0;
    __syncthreads();

    for (int it = 0; it < S1; it++) {
        int far = s_far;
        float cx = base[far * 3 + 0];
        float cy = base[far * 3 + 1];
        float cz = base[far * 3 + 2];
        if (tid == 0) {
            outxyz[((size_t)b * S1 + it) * 3 + 0] = cx;
            outxyz[((size_t)b * S1 + it) * 3 + 1] = cy;
            outxyz[((size_t)b * S1 + it) * 3 + 2] = cz;
        }
        u64 ncx = pk2(-cx, -cx), ncy = pk2(-cy, -cy), ncz = pk2(-cz, -cz);
        float bv = -1.0f; int bj = 0;
#pragma unroll
        for (int h = 0; h < 4; h++) {
            u64 dx = add2(px2[h], ncx);
            u64 dy = add2(py2[h], ncy);
            u64 dz = add2(pz2[h], ncz);
            u64 d2 = mul2(dx, dx);
            fma2(d2, dy, dy);
            fma2(d2, dz, dz);
            float2 dd = up2(d2);
            float nd0 = fminf(dist[2 * h], dd.x);     dist[2 * h] = nd0;
            if (nd0 > bv) { bv = nd0; bj = 2 * h; }
            float nd1 = fminf(dist[2 * h + 1], dd.y); dist[2 * h + 1] = nd1;
            if (nd1 > bv) { bv = nd1; bj = 2 * h + 1; }
        }
        int bi = tid + bj * 1024;
        for (int off = 16; off; off >>= 1) {
            float ov = __shfl_down_sync(0xffffffffu, bv, off);
            int   oi = __shfl_down_sync(0xffffffffu, bi, off);
            if (ov > bv || (ov == bv && oi < bi)) { bv = ov; bi = oi; }
        }
        if ((tid & 31) == 0) { s_v[tid >> 5] = bv; s_i[tid >> 5] = bi; }
        __syncthreads();
        if (tid < 32) {
            bv = s_v[tid]; bi = s_i[tid];
            for (int off = 16; off; off >>= 1) {
                float ov = __shfl_down_sync(0xffffffffu, bv, off);
                int   oi = __shfl_down_sync(0xffffffffu, bi, off);
                if (ov > bv || (ov == bv && oi < bi)) { bv = ov; bi = oi; }
            }
            if (tid == 0) s_far = bi;
        }
        __syncthreads();
    }
}

// ---------------- FPS (1 pt/thread, scalar; S1 points -> S2 samples) ----------------
__global__ void __launch_bounds__(1024) fps1_kernel(const float* __restrict__ pts,
                                                    float* __restrict__ outxyz) {
    int b = blockIdx.x, tid = threadIdx.x;
    const float* base = pts + (size_t)b * S1 * 3;
    float px = base[tid * 3 + 0], py = base[tid * 3 + 1], pz = base[tid * 3 + 2];
    float dist = 1e10f;
    __shared__ int   s_far;
    __shared__ float s_v[32];
    __shared__ int   s_i[32];
    if (tid == 0) s_far = 0;
    __syncthreads();

    for (int it = 0; it < S2; it++) {
        int far = s_far;
        float cx = base[far * 3 + 0];
        float cy = base[far * 3 + 1];
        float cz = base[far * 3 + 2];
        if (tid == 0) {
            outxyz[((size_t)b * S2 + it) * 3 + 0] = cx;
            outxyz[((size_t)b * S2 + it) * 3 + 1] = cy;
            outxyz[((size_t)b * S2 + it) * 3 + 2] = cz;
        }
        float dx = __fsub_rn(px, cx);
        float dy = __fsub_rn(py, cy);
        float dz = __fsub_rn(pz, cz);
        float d = fmaf(dz, dz, fmaf(dy, dy, __fmul_rn(dx, dx)));
        dist = fminf(dist, d);
        float bv = dist; int bi = tid;
        for (int off = 16; off; off >>= 1) {
            float ov = __shfl_down_sync(0xffffffffu, bv, off);
            int   oi = __shfl_down_sync(0xffffffffu, bi, off);
            if (ov > bv || (ov == bv && oi < bi)) { bv = ov; bi = oi; }
        }
        if ((tid & 31) == 0) { s_v[tid >> 5] = bv; s_i[tid >> 5] = bi; }
        __syncthreads();
        if (tid < 32) {
            bv = s_v[tid]; bi = s_i[tid];
            for (int off = 16; off; off >>= 1) {
                float ov = __shfl_down_sync(0xffffffffu, bv, off);
                int   oi = __shfl_down_sync(0xffffffffu, bi, off);
                if (ov > bv || (ov == bv && oi < bi)) { bv = ov; bi = oi; }
            }
            if (tid == 0) s_far = bi;
        }
        __syncthreads();
    }
}

// ---------------- ball query ----------------
__global__ void ball_kernel(const float* __restrict__ centers, const float* __restrict__ pts,
                            int nptsB, int SQ, float r2, int nsample,
                            int* __restrict__ out, int Qtot) {
    __shared__ int buf[8][32];
    int gw   = (blockIdx.x * blockDim.x + threadIdx.x) >> 5;
    int wl   = (threadIdx.x >> 5) & 7;
    int lane = threadIdx.x & 31;
    if (gw >= Qtot) return;
    int b = gw / SQ;
    const float* c3 = centers + (size_t)gw * 3;
    float cx = c3[0], cy = c3[1], cz = c3[2];
    float sc = sumsq3(cx, cy, cz);
    const float* pb = pts + (size_t)b * nptsB * 3;
    int kept = 0;
    for (int j0 = 0; j0 < nptsB; j0 += 32) {
        int p = j0 + lane;
        float d = sqdist_cancel(sc, cx, cy, cz, pb[p * 3], pb[p * 3 + 1], pb[p * 3 + 2]);
        bool in = !(d > r2);
        unsigned m = __ballot_sync(0xffffffffu, in);
        int rank = kept + __popc(m & ((1u << lane) - 1u));
        if (in && rank < nsample) buf[wl][rank] = p;
        kept += __popc(m);
        if (kept >= nsample) break;
    }
    __syncwarp();
    int first = buf[wl][0];
    for (int i = lane; i < nsample; i += 32)
        out[(size_t)gw * nsample + i] = (i < kept) ? buf[wl][i] : first;
}

// ---------------- 3-NN ----------------
__global__ void nn3_kernel(const float* __restrict__ qpts, int qstride,
                           const float* __restrict__ pts, int nptsB, int SQ,
                           int* __restrict__ oi, float* __restrict__ ow, int Qtot) {
    int gw   = (blockIdx.x * blockDim.x + threadIdx.x) >> 5;
    int lane = threadIdx.x & 31;
    if (gw >= Qtot) return;
    int b = gw / SQ;
    const float* qp = qpts + (size_t)gw * qstride;
    float cx = qp[0], cy = qp[1], cz = qp[2];
    float sc = sumsq3(cx, cy, cz);
    const float* pb = pts + (size_t)b * nptsB * 3;
    float D0 = FLT_MAX, D1 = FLT_MAX, D2 = FLT_MAX;
    int   I0 = 0x7fffffff, I1 = 0x7fffffff, I2 = 0x7fffffff;
    for (int p = lane; p < nptsB; p += 32) {
        float d = sqdist_cancel(sc, cx, cy, cz, pb[p * 3], pb[p * 3 + 1], pb[p * 3 + 2]);
        top3_insert(d, p, D0, D1, D2, I0, I1, I2);
    }
    for (int off = 16; off; off >>= 1) {
        float e0 = __shfl_down_sync(0xffffffffu, D0, off);
        float e1 = __shfl_down_sync(0xffffffffu, D1, off);
        float e2 = __shfl_down_sync(0xffffffffu, D2, off);
        int   f0 = __shfl_down_sync(0xffffffffu, I0, off);
        int   f1 = __shfl_down_sync(0xffffffffu, I1, off);
        int   f2 = __shfl_down_sync(0xffffffffu, I2, off);
        top3_insert(e0, f0, D0, D1, D2, I0, I1, I2);
        top3_insert(e1, f1, D0, D1, D2, I0, I1, I2);
        top3_insert(e2, f2, D0, D1, D2, I0, I1, I2);
    }
    if (lane == 0) {
        float r0 = 1.0f / (D0 + 1e-8f);
        float r1 = 1.0f / (D1 + 1e-8f);
        float r2 = 1.0f / (D2 + 1e-8f);
        float s = (r0 + r1) + r2;
        oi[(size_t)gw * 3 + 0] = I0; oi[(size_t)gw * 3 + 1] = I1; oi[(size_t)gw * 3 + 2] = I2;
        ow[(size_t)gw * 3 + 0] = r0 / s; ow[(size_t)gw * 3 + 1] = r1 / s; ow[(size_t)gw * 3 + 2] = r2 / s;
    }
}

// ---------------- SA1: gather + MLP(27->64->128->128) + max over 16 ----------------
__global__ void __launch_bounds__(128) sa1_kernel(const float* __restrict__ b0,
                                                  const float* __restrict__ b1,
                                                  const float* __restrict__ b2) {
    __shared__ __align__(16) float g  [16][28];
    __shared__ __align__(16) float h1s[16][64];
    __shared__ __align__(16) float h2s[16][128];
    __shared__ int   sidx[16];
    __shared__ float ctr[3];
    int q = blockIdx.x;
    int b = q >> 10;
    int tid = threadIdx.x;
    if (tid < 16) sidx[tid] = g_ball1[q * 16 + tid];
    if (tid >= 16 && tid < 19) ctr[tid - 16] = g_l1xyz[(size_t)q * 3 + (tid - 16)];
    __syncthreads();
    for (int e = tid; e < 16 * 28; e += 128) {
        int r = e / 28, c = e - r * 28;
        float v = 0.0f;
        if (c < 27) {
            const float* row = g_xt + ((size_t)(b * N0 + sidx[r])) * CX;
            v = (c < 3) ? (row[c] - ctr[c]) : row[c - 3];
        }
        g[r][c] = v;
    }
    __syncthreads();
    {   // layer1: K=28, O=64
        int og = tid & 15, rg = tid >> 4, o0 = og * 4;
        u64 acc[2][4];
#pragma unroll
        for (int r = 0; r < 2; r++)
#pragma unroll
            for (int j = 0; j < 4; j++) acc[r][j] = 0ull;
        mm4p<2>(g_wt + OFF_SA1_0, 64, og, 28, &g[rg * 2][0], 28, acc);
#pragma unroll
        for (int r = 0; r < 2; r++)
#pragma unroll
            for (int j = 0; j < 4; j++) {
                float2 f = up2(acc[r][j]);
                h1s[rg * 2 + r][o0 + j] = fmaxf((f.x + f.y) + b0[o0 + j], 0.0f);
            }
    }
    __syncthreads();
    {   // layer2: K=64, O=128
        int og = tid & 31, rg = tid >> 5, o0 = og * 4;
        u64 acc[4][4];
#pragma unroll
        for (int r = 0; r < 4; r++)
#pragma unroll
            for (int j = 0; j < 4; j++) acc[r][j] = 0ull;
        mm4p<4>(g_wt + OFF_SA1_1, 128, og, 64, &h1s[rg * 4][0], 64, acc);
#pragma unroll
        for (int r = 0; r < 4; r++)
#pragma unroll
            for (int j = 0; j < 4; j++) {
                float2 f = up2(acc[r][j]);
                h2s[rg * 4 + r][o0 + j] = fmaxf((f.x + f.y) + b1[o0 + j], 0.0f);
            }
    }
    __syncthreads();
    {   // layer3: K=128, O=128, fused max over 16 rows
        int o = tid;
        u64 acc[16];
#pragma unroll
        for (int r = 0; r < 16; r++) acc[r] = 0ull;
        mmcolp<16>(g_wt + OFF_SA1_2, 128, o, 128, &h2s[0][0], 128, acc);
        float2 f0 = up2(acc[0]);
        float m = f0.x + f0.y;
#pragma unroll
        for (int r = 1; r < 16; r++) {
            float2 f = up2(acc[r]);
            m = fmaxf(m, f.x + f.y);
        }
        g_l1p[(size_t)q * 128 + o] = fmaxf(m + b2[o], 0.0f);
    }
}

// ---------------- SA2: gather + MLP(131->128->256) + max over 32 ----------------
__global__ void __launch_bounds__(256) sa2_kernel(const float* __restrict__ b0,
                                                  const float* __restrict__ b1) {
    __shared__ __align__(16) float g  [32][132];
    __shared__ __align__(16) float h1s[32][128];
    __shared__ int   sidx[32];
    __shared__ float ctr[3];
    int q = blockIdx.x;
    int b = q >> 9;
    int tid = threadIdx.x;
    if (tid < 32) sidx[tid] = g_ball2[q * 32 + tid];
    if (tid >= 32 && tid < 35) ctr[tid - 32] = g_l2xyz[(size_t)q * 3 + (tid - 32)];
    __syncthreads();
    for (int e = tid; e < 32 * 132; e += 256) {
        int r = e / 132, c = e - r * 132;
        float v = 0.0f;
        if (c < 131) {
            int p = sidx[r];
            if (c < 3) v = g_l1xyz[((size_t)b * S1 + p) * 3 + c] - ctr[c];
            else       v = g_l1p[((size_t)b * S1 + p) * 128 + (c - 3)];
        }
        g[r][c] = v;
    }
    __syncthreads();
    {   // layer1: K=132, O=128
        int og = tid & 31, rg = tid >> 5, o0 = og * 4;
        u64 acc[4][4];
#pragma unroll
        for (int r = 0; r < 4; r++)
#pragma unroll
            for (int j = 0; j < 4; j++) acc[r][j] = 0ull;
        mm4p<4>(g_wt + OFF_SA2_0, 128, og, 132, &g[rg * 4][0], 132, acc);
#pragma unroll
        for (int r = 0; r < 4; r++)
#pragma unroll
            for (int j = 0; j < 4; j++) {
                float2 f = up2(acc[r][j]);
                h1s[rg * 4 + r][o0 + j] = fmaxf((f.x + f.y) + b0[o0 + j], 0.0f);
            }
    }
    __syncthreads();
    {   // layer2: K=128, O=256, fused max over 32 rows
        int o = tid;
        u64 acc[32];
#pragma unroll
        for (int r = 0; r < 32; r++) acc[r] = 0ull;
        mmcolp<32>(g_wt + OFF_SA2_1, 256, o, 128, &h1s[0][0], 128, acc);
        float2 f0 = up2(acc[0]);
        float m = f0.x + f0.y;
#pragma unroll
        for (int r = 1; r < 32; r++) {
            float2 f = up2(acc[r]);
            m = fmaxf(m, f.x + f.y);
        }
        g_l2p[(size_t)q * 256 + o] = fmaxf(m + b1[o], 0.0f);
    }
}

// ---------------- FP2: interp(l2->l1) + concat + MLP(384->256->256) ----------------
__global__ void __launch_bounds__(256) fp2_kernel(const float* __restrict__ b0,
                                                  const float* __restrict__ b1) {
    __shared__ __align__(16) float feat[16][384];
    __shared__ __align__(16) float h1s [16][256];
    __shared__ int   nni[16][3];
    __shared__ float nnw[16][3];
    int row0 = blockIdx.x * 16;
    int b = row0 >> 10;
    int tid = threadIdx.x;
    if (tid < 48)                   nni[tid / 3][tid % 3] = g_nn2i[(size_t)row0 * 3 + tid];
    else if (tid < 96) { int t = tid - 48; nnw[t / 3][t % 3] = g_nn2w[(size_t)row0 * 3 + t]; }
    for (int e = tid; e < 16 * 128; e += 256) {
        int r = e >> 7, c = e & 127;
        feat[r][c] = g_l1p[((size_t)row0 + r) * 128 + c];
    }
    __syncthreads();
    {
        const float* p2 = g_l2p + (size_t)b * S2 * 256;
        int c = tid;
#pragma unroll 4
        for (int r = 0; r < 16; r++) {
            float v = p2[(size_t)nni[r][0] * 256 + c] * nnw[r][0];
            v += p2[(size_t)nni[r][1] * 256 + c] * nnw[r][1];
            v += p2[(size_t)nni[r][2] * 256 + c] * nnw[r][2];
            feat[r][128 + c] = v;
        }
    }
    __syncthreads();
    int og = tid & 63, rg = tid >> 6, o0 = og * 4;
    {   // layer1: K=384, O=256
        u64 acc[4][4];
#pragma unroll
        for (int r = 0; r < 4; r++)
#pragma unroll
            for (int j = 0; j < 4; j++) acc[r][j] = 0ull;
        mm4p<4>(g_wt + OFF_FP2_0, 256, og, 384, &feat[rg * 4][0], 384, acc);
#pragma unroll
        for (int r = 0; r < 4; r++)
#pragma unroll
            for (int j = 0; j < 4; j++) {
                float2 f = up2(acc[r][j]);
                h1s[rg * 4 + r][o0 + j] = fmaxf((f.x + f.y) + b0[o0 + j], 0.0f);
            }
    }
    __syncthreads();
    {   // layer2: K=256, O=256
        u64 acc[4][4];
#pragma unroll
        for (int r = 0; r < 4; r++)
#pragma unroll
            for (int j = 0; j < 4; j++) acc[r][j] = 0ull;
        mm4p<4>(g_wt + OFF_FP2_1, 256, og, 256, &h1s[rg * 4][0], 256, acc);
#pragma unroll
        for (int r = 0; r < 4; r++)
#pragma unroll
            for (int j = 0; j < 4; j++) {
                float2 f = up2(acc[r][j]);
                g_l1p2[((size_t)row0 + rg * 4 + r) * 256 + o0 + j] =
                    fmaxf((f.x + f.y) + b1[o0 + j], 0.0f);
            }
    }
}

// ---------------- FP1: concat(l0_xyz, x, interp) + MLP(283->256->256) -> out ----------------
constexpr int FP1_ROWS = 32;
constexpr int FP1_FEAT = FP1_ROWS * 284;
constexpr int FP1_SMEM = (FP1_FEAT + FP1_ROWS * 256) * 4;

__global__ void __launch_bounds__(256) fp1_kernel(const float* __restrict__ b0,
                                                  const float* __restrict__ b1,
                                                  float* __restrict__ out) {
    extern __shared__ float sdyn[];
    float* feat = sdyn;                 // [32][284]
    float* h1s  = sdyn + FP1_FEAT;      // [32][256]
    __shared__ int   nni[FP1_ROWS][3];
    __shared__ float nnw[FP1_ROWS][3];
    int row0 = blockIdx.x * FP1_ROWS;
    int b = row0 >> 13;
    int tid = threadIdx.x;
    if (tid < 96)                    nni[tid / 3][tid % 3] = g_nn1i[(size_t)row0 * 3 + tid];
    else if (tid < 192) { int t = tid - 96; nnw[t / 3][t % 3] = g_nn1w[(size_t)row0 * 3 + t]; }
    for (int e = tid; e < FP1_ROWS * 27; e += 256) {
        int r = e / 27, c = e - r * 27;
        const float* row = g_xt + (size_t)(row0 + r) * CX;
        feat[r * 284 + c] = (c < 3) ? row[c] : row[c - 3];
    }
    if (tid < FP1_ROWS) feat[tid * 284 + 283] = 0.0f;
    __syncthreads();
    {
        const float* p1 = g_l1p2 + (size_t)b * S1 * 256;
        int c = tid;
#pragma unroll 4
        for (int r = 0; r < FP1_ROWS; r++) {
            float v = p1[(size_t)nni[r][0] * 256 + c] * nnw[r][0];
            v += p1[(size_t)nni[r][1] * 256 + c] * nnw[r][1];
            v += p1[(size_t)nni[r][2] * 256 + c] * nnw[r][2];
            feat[r * 284 + 27 + c] = v;
        }
    }
    __syncthreads();
    int og = tid & 63, rg = tid >> 6, o0 = og * 4;   // 4 row-groups x 8 rows
    {   // layer1: K=284, O=256
        u64 acc[8][4];
#pragma unroll
        for (int r = 0; r < 8; r++)
#pragma unroll
            for (int j = 0; j < 4; j++) acc[r][j] = 0ull;
        mm4p<8>(g_wt + OFF_FP1_0, 256, og, 284, feat + rg * 8 * 284, 284, acc);
#pragma unroll
        for (int r = 0; r < 8; r++)
#pragma unroll
            for (int j = 0; j < 4; j++) {
                float2 f = up2(acc[r][j]);
                h1s[(rg * 8 + r) * 256 + o0 + j] = fmaxf((f.x + f.y) + b0[o0 + j], 0.0f);
            }
    }
    __syncthreads();
    {   // layer2: K=256, O=256
        u64 acc[8][4];
#pragma unroll
        for (int r = 0; r < 8; r++)
#pragma unroll
            for (int j = 0; j < 4; j++) acc[r][j] = 0ull;
        mm4p<8>(g_wt + OFF_FP1_1, 256, og, 256, h1s + rg * 8 * 256, 256, acc);
#pragma unroll
        for (int r = 0; r < 8; r++)
#pragma unroll
            for (int j = 0; j < 4; j++) {
                float2 f = up2(acc[r][j]);
                out[((size_t)row0 + rg * 8 + r) * 256 + o0 + j] =
                    fmaxf((f.x + f.y) + b1[o0 + j], 0.0f);
            }
    }
}

// ---------------- launch ----------------
extern "C" void kernel_launch(void* const* d_in, const int* in_sizes, int n_in,
                              void* d_out, int out_size) {
    const float* xyz = (const float*)d_in[0];
    const float* sa1_b0 = (const float*)d_in[2];
    const float* sa1_b1 = (const float*)d_in[4];
    const float* sa1_b2 = (const float*)d_in[6];
    const float* sa2_b0 = (const float*)d_in[8];
    const float* sa2_b1 = (const float*)d_in[10];
    const float* fp2_b0 = (const float*)d_in[12];
    const float* fp2_b1 = (const float*)d_in[14];
    const float* fp1_b0 = (const float*)d_in[16];
    const float* fp1_b1 = (const float*)d_in[18];
    float* out = (float*)d_out;

    const float r2_1 = (float)(0.035 * 0.035);
    const float r2_2 = (float)(0.0176 * 0.0176);

    transpose_x_kernel<<<(B * CX * N0 + 255) / 256, 256>>>(xyz);

    WT9 w;
    const int offs[9]  = { OFF_SA1_0, OFF_SA1_1, OFF_SA1_2, OFF_SA2_0, OFF_SA2_1,
                           OFF_FP2_0, OFF_FP2_1, OFF_FP1_0, OFF_FP1_1 };
    const int Os[9]    = { 64, 128, 128, 128, 256, 256, 256, 256, 256 };
    const int Ks[9]    = { 27, 64, 128, 131, 128, 384, 256, 283, 256 };
    const int Kpads[9] = { 28, 64, 128, 132, 128, 384, 256, 284, 256 };
    const int widx[9]  = { 1, 3, 5, 7, 9, 11, 13, 15, 17 };
    int total = 0;
    for (int i = 0; i < 9; i++) {
        w.W[i] = (const float*)d_in[widx[i]];
        w.off[i] = offs[i]; w.O[i] = Os[i]; w.K[i] = Ks[i]; w.Kpad[i] = Kpads[i];
        total += Kpads[i] * Os[i];
    }
    transpose_w9_kernel<<<(total + 255) / 256, 256>>>(w);

    float* l0 = nullptr; float* l1 = nullptr; float* l2 = nullptr;
    cudaGetSymbolAddress((void**)&l0, g_l0xyz);
    cudaGetSymbolAddress((void**)&l1, g_l1xyz);
    cudaGetSymbolAddress((void**)&l2, g_l2xyz);
    int* ball1 = nullptr; cudaGetSymbolAddress((void**)&ball1, g_ball1);
    int* ball2 = nullptr; cudaGetSymbolAddress((void**)&ball2, g_ball2);
    int* nn2i = nullptr; cudaGetSymbolAddress((void**)&nn2i, g_nn2i);
    float* nn2w = nullptr; cudaGetSymbolAddress((void**)&nn2w, g_nn2w);
    int* nn1i = nullptr; cudaGetSymbolAddress((void**)&nn1i, g_nn1i);
    float* nn1w = nullptr; cudaGetSymbolAddress((void**)&nn1w, g_nn1w);

    // SA1
    fps8_kernel<<<B, 1024>>>(l0, l1);
    ball_kernel<<<(B * S1 * 32 + 255) / 256, 256>>>(l1, l0, N0, S1, r2_1, K1, ball1, B * S1);
    sa1_kernel<<<B * S1, 128>>>(sa1_b0, sa1_b1, sa1_b2);

    // SA2
    fps1_kernel<<<B, 1024>>>(l1, l2);
    ball_kernel<<<(B * S2 * 32 + 255) / 256, 256>>>(l2, l1, S1, S2, r2_2, K2, ball2, B * S2);
    sa2_kernel<<<B * S2, 256>>>(sa2_b0, sa2_b1);

    // FP2
    nn3_kernel<<<(B * S1 * 32 + 255) / 256, 256>>>(l1, 3, l2, S2, S1, nn2i, nn2w, B * S1);
    fp2_kernel<<<B * S1 / 16, 256>>>(fp2_b0, fp2_b1);

    // FP1
    nn3_kernel<<<(B * N0 * 32 + 255) / 256, 256>>>(l0, 3, l1, S1, N0, nn1i, nn1w, B * N0);
    cudaFuncSetAttribute(fp1_kernel, cudaFuncAttributeMaxDynamicSharedMemorySize, FP1_SMEM);
    fp1_kernel<<<B * N0 / FP1_ROWS, 256, FP1_SMEM>>>(fp1_b0, fp1_b1, out);
}

// round 5
// speedup vs baseline: 1.5609x; 1.5609x over previous
#include <cuda_runtime.h>
#include <cstdint>
#include <cstddef>
#include <float.h>

// ---------------- problem constants ----------------
constexpr int B   = 8;
constexpr int N0  = 8192;
constexpr int CX  = 24;
constexpr int S1  = 1024, K1 = 16;
constexpr int S2  = 512,  K2 = 32;

// ---------------- scratch ----------------
__device__ float  g_xt    [B * N0 * CX];
__device__ float4 g_l0xyz4[B * N0];
__device__ float4 g_l1xyz4[B * S1];
__device__ float4 g_l2xyz4[B * S2];
__device__ int    g_ball1 [B * S1 * K1];
__device__ float  g_l1p   [B * S1 * 128];
__device__ int    g_ball2 [B * S2 * K2];
__device__ float  g_l2p   [B * S2 * 256];
__device__ int    g_nn2i  [B * S1 * 3];
__device__ float  g_nn2w  [B * S1 * 3];
__device__ float  g_l1p2  [B * S1 * 256];
__device__ int    g_nn1i  [B * N0 * 3];
__device__ float  g_nn1w  [B * N0 * 3];
__device__ float  g_wt    [378112];

constexpr int OFF_SA1_0 = 0;        // 28 x 64
constexpr int OFF_SA1_1 = 1792;     // 64 x 128
constexpr int OFF_SA1_2 = 9984;     // 128 x 128
constexpr int OFF_SA2_0 = 26368;    // 132 x 128
constexpr int OFF_SA2_1 = 43264;    // 128 x 256
constexpr int OFF_FP2_0 = 76032;    // 384 x 256
constexpr int OFF_FP2_1 = 174336;   // 256 x 256
constexpr int OFF_FP1_0 = 239872;   // 284 x 256
constexpr int OFF_FP1_1 = 312576;   // 256 x 256

// ---------------- numeric helpers (pinned op order) ----------------
__device__ __forceinline__ float sumsq3(float x, float y, float z) {
    return fmaf(z, z, fmaf(y, y, __fmul_rn(x, x)));
}
__device__ __forceinline__ float sqdist_cancel(float sc, float cx, float cy, float cz,
                                               float px, float py, float pz) {
    float sp  = sumsq3(px, py, pz);
    float dot = fmaf(cz, pz, fmaf(cy, py, __fmul_rn(cx, px)));
    return __fsub_rn(__fadd_rn(sc, sp), __fmul_rn(2.0f, dot));
}
__device__ __forceinline__ void top3_insert(float d, int p,
                                            float& D0, float& D1, float& D2,
                                            int& I0, int& I1, int& I2) {
    if (d < D2 || (d == D2 && p < I2)) {
        if (d < D1 || (d == D1 && p < I1)) {
            D2 = D1; I2 = I1;
            if (d < D0 || (d == D0 && p < I0)) { D1 = D0; I1 = I0; D0 = d; I0 = p; }
            else                               { D1 = d;  I1 = p; }
        } else { D2 = d; I2 = p; }
    }
}

// warp argmax of non-negative float value with min-index tie-break (exact).
__device__ __forceinline__ void warp_argmax(float& v, int& i) {
    unsigned vb = __float_as_uint(v);                       // v >= 0 -> bits monotonic
    unsigned m  = __reduce_max_sync(0xffffffffu, vb);
    unsigned ci = (vb == m) ? (unsigned)i : 0xffffffffu;
    unsigned bi = __reduce_min_sync(0xffffffffu, ci);
    v = __uint_as_float(m);
    i = (int)bi;
}

// acc[r][j] += sum_k in[r][k] * Wt[k][og*4+j]
template <int NR>
__device__ __forceinline__ void mm4(const float* __restrict__ wt, int O, int og, int KP,
                                    const float* __restrict__ in0, int ld, float (&acc)[NR][4]) {
    const float4* wt4 = reinterpret_cast<const float4*>(wt);
    const int OV4 = O >> 2;
#pragma unroll 2
    for (int k = 0; k < KP; k += 4) {
        float4 wa = wt4[(k + 0) * OV4 + og];
        float4 wb = wt4[(k + 1) * OV4 + og];
        float4 wc = wt4[(k + 2) * OV4 + og];
        float4 wd = wt4[(k + 3) * OV4 + og];
#pragma unroll
        for (int r = 0; r < NR; r++) {
            const float4 gv = *reinterpret_cast<const float4*>(in0 + r * ld + k);
            acc[r][0] += gv.x * wa.x; acc[r][0] += gv.y * wb.x; acc[r][0] += gv.z * wc.x; acc[r][0] += gv.w * wd.x;
            acc[r][1] += gv.x * wa.y; acc[r][1] += gv.y * wb.y; acc[r][1] += gv.z * wc.y; acc[r][1] += gv.w * wd.y;
            acc[r][2] += gv.x * wa.z; acc[r][2] += gv.y * wb.z; acc[r][2] += gv.z * wc.z; acc[r][2] += gv.w * wd.z;
            acc[r][3] += gv.x * wa.w; acc[r][3] += gv.y * wb.w; acc[r][3] += gv.z * wc.w; acc[r][3] += gv.w * wd.w;
        }
    }
}

// acc[r] += sum_k in[r][k] * Wt[k][o]
template <int NR>
__device__ __forceinline__ void mmcol(const float* __restrict__ wt, int O, int o, int KP,
                                      const float* __restrict__ in0, int ld, float (&acc)[NR]) {
#pragma unroll 2
    for (int k = 0; k < KP; k += 4) {
        float wa = wt[(k + 0) * O + o];
        float wb = wt[(k + 1) * O + o];
        float wc = wt[(k + 2) * O + o];
        float wd = wt[(k + 3) * O + o];
#pragma unroll
        for (int r = 0; r < NR; r++) {
            const float4 gv = *reinterpret_cast<const float4*>(in0 + r * ld + k);
            acc[r] += gv.x * wa; acc[r] += gv.y * wb; acc[r] += gv.z * wc; acc[r] += gv.w * wd;
        }
    }
}

// ---------------- prep ----------------
__global__ void transpose_x_kernel(const float* __restrict__ xyz) {
    int i = blockIdx.x * blockDim.x + threadIdx.x;   // over B*CX*N0
    if (i >= B * CX * N0) return;
    int b = i / (CX * N0);
    int rem = i - b * (CX * N0);
    int c = rem / N0;
    int n = rem - c * N0;
    float v = xyz[i];
    g_xt[((size_t)b * N0 + n) * CX + c] = v;
    if (c < 3) {
        float* p4 = (float*)&g_l0xyz4[(size_t)b * N0 + n];
        p4[c] = v;
        if (c == 0) p4[3] = 0.0f;
    }
}

struct WT9 {
    const float* W[9];
    int off[9], O[9], K[9], Kpad[9];
};
__global__ void transpose_w9_kernel(WT9 w) {
    int i = blockIdx.x * blockDim.x + threadIdx.x;
#pragma unroll
    for (int s = 0; s < 9; s++) {
        int n = w.Kpad[s] * w.O[s];
        if (i < n) {
            int k = i / w.O[s], o = i - k * w.O[s];
            g_wt[w.off[s] + i] = (k < w.K[s]) ? w.W[s][o * w.K[s] + k] : 0.0f;
            return;
        }
        i -= n;
    }
}

// ---------------- FPS: 1 block per batch, PPT points per thread ----------------
template <int PPT, int NPTS, int NP>
__global__ void __launch_bounds__(1024) fps_kernel(const float4* __restrict__ pts4,
                                                   float4* __restrict__ out4) {
    int b = blockIdx.x, tid = threadIdx.x;
    const float4* base = pts4 + (size_t)b * NPTS;
    float px[PPT], py[PPT], pz[PPT], dist[PPT];
#pragma unroll
    for (int j = 0; j < PPT; j++) {
        float4 P = base[tid + j * 1024];
        px[j] = P.x; py[j] = P.y; pz[j] = P.z;
        dist[j] = 1e10f;
    }
    __shared__ int   s_far;
    __shared__ float s_v[32];
    __shared__ int   s_i[32];
    if (tid == 0) s_far = 0;
    __syncthreads();

    for (int it = 0; it < NP; it++) {
        int far = s_far;
        float4 C = base[far];
        float cx = C.x, cy = C.y, cz = C.z;
        if (tid == 0) out4[(size_t)b * NP + it] = make_float4(cx, cy, cz, 0.0f);
        float bv = -1.0f; int bj = 0;
#pragma unroll
        for (int j = 0; j < PPT; j++) {
            float dx = __fsub_rn(px[j], cx);
            float dy = __fsub_rn(py[j], cy);
            float dz = __fsub_rn(pz[j], cz);
            float d = fmaf(dz, dz, fmaf(dy, dy, __fmul_rn(dx, dx)));
            float nd = fminf(dist[j], d);
            dist[j] = nd;
            if (nd > bv) { bv = nd; bj = j; }   // ascending j => lowest p for equal values
        }
        int bi = tid + bj * 1024;
        warp_argmax(bv, bi);
        if ((tid & 31) == 0) { s_v[tid >> 5] = bv; s_i[tid >> 5] = bi; }
        __syncthreads();
        if (tid < 32) {
            bv = s_v[tid]; bi = s_i[tid];
            warp_argmax(bv, bi);
            if (tid == 0) s_far = bi;
        }
        __syncthreads();
    }
}

// ---------------- ball query: 1 warp per query, ascending index order ----------------
__global__ void ball_kernel(const float4* __restrict__ centers, const float4* __restrict__ pts4,
                            int nptsB, int SQ, float r2, int nsample,
                            int* __restrict__ out, int Qtot) {
    __shared__ int buf[8][32];
    int gw   = (blockIdx.x * blockDim.x + threadIdx.x) >> 5;
    int wl   = (threadIdx.x >> 5) & 7;
    int lane = threadIdx.x & 31;
    if (gw >= Qtot) return;
    int b = gw / SQ;
    float4 C = centers[gw];
    float cx = C.x, cy = C.y, cz = C.z;
    float sc = sumsq3(cx, cy, cz);
    const float4* pb = pts4 + (size_t)b * nptsB;
    int kept = 0;
    for (int j0 = 0; j0 < nptsB; j0 += 32) {
        int p = j0 + lane;
        float4 P = pb[p];
        float d = sqdist_cancel(sc, cx, cy, cz, P.x, P.y, P.z);
        bool in = !(d > r2);
        unsigned m = __ballot_sync(0xffffffffu, in);
        int rank = kept + __popc(m & ((1u << lane) - 1u));
        if (in && rank < nsample) buf[wl][rank] = p;
        kept += __popc(m);
        if (kept >= nsample) break;
    }
    __syncwarp();
    int first = buf[wl][0];
    for (int i = lane; i < nsample; i += 32)
        out[(size_t)gw * nsample + i] = (i < kept) ? buf[wl][i] : first;
}

// ---------------- 3-NN: 1 warp per query, strided coalesced scan ----------------
__global__ void nn3_kernel(const float4* __restrict__ qpts4,
                           const float4* __restrict__ pts4, int nptsB, int SQ,
                           int* __restrict__ oi, float* __restrict__ ow, int Qtot) {
    int gw   = (blockIdx.x * blockDim.x + threadIdx.x) >> 5;
    int lane = threadIdx.x & 31;
    if (gw >= Qtot) return;
    int b = gw / SQ;
    float4 Q = qpts4[gw];
    float cx = Q.x, cy = Q.y, cz = Q.z;
    float sc = sumsq3(cx, cy, cz);
    const float4* pb = pts4 + (size_t)b * nptsB;
    float D0 = FLT_MAX, D1 = FLT_MAX, D2 = FLT_MAX;
    int   I0 = 0x7fffffff, I1 = 0x7fffffff, I2 = 0x7fffffff;
    for (int p = lane; p < nptsB; p += 32) {
        float4 P = pb[p];
        float d = sqdist_cancel(sc, cx, cy, cz, P.x, P.y, P.z);
        top3_insert(d, p, D0, D1, D2, I0, I1, I2);
    }
    for (int off = 16; off; off >>= 1) {
        float e0 = __shfl_down_sync(0xffffffffu, D0, off);
        float e1 = __shfl_down_sync(0xffffffffu, D1, off);
        float e2 = __shfl_down_sync(0xffffffffu, D2, off);
        int   f0 = __shfl_down_sync(0xffffffffu, I0, off);
        int   f1 = __shfl_down_sync(0xffffffffu, I1, off);
        int   f2 = __shfl_down_sync(0xffffffffu, I2, off);
        top3_insert(e0, f0, D0, D1, D2, I0, I1, I2);
        top3_insert(e1, f1, D0, D1, D2, I0, I1, I2);
        top3_insert(e2, f2, D0, D1, D2, I0, I1, I2);
    }
    if (lane == 0) {
        float r0 = 1.0f / (D0 + 1e-8f);
        float r1 = 1.0f / (D1 + 1e-8f);
        float r2 = 1.0f / (D2 + 1e-8f);
        float s = (r0 + r1) + r2;
        oi[(size_t)gw * 3 + 0] = I0; oi[(size_t)gw * 3 + 1] = I1; oi[(size_t)gw * 3 + 2] = I2;
        ow[(size_t)gw * 3 + 0] = r0 / s; ow[(size_t)gw * 3 + 1] = r1 / s; ow[(size_t)gw * 3 + 2] = r2 / s;
    }
}

// ---------------- SA1: gather + MLP(27->64->128->128) + max over 16 ----------------
__global__ void __launch_bounds__(128) sa1_kernel(const float* __restrict__ b0,
                                                  const float* __restrict__ b1,
                                                  const float* __restrict__ b2) {
    __shared__ __align__(16) float g  [16][28];
    __shared__ __align__(16) float h1s[16][64];
    __shared__ __align__(16) float h2s[16][128];
    __shared__ int   sidx[16];
    __shared__ float ctr[3];
    int q = blockIdx.x;
    int b = q >> 10;
    int tid = threadIdx.x;
    if (tid < 16) sidx[tid] = g_ball1[q * 16 + tid];
    if (tid >= 16 && tid < 19) ctr[tid - 16] = ((const float*)&g_l1xyz4[q])[tid - 16];
    __syncthreads();
    for (int e = tid; e < 16 * 28; e += 128) {
        int r = e / 28, c = e - r * 28;
        float v = 0.0f;
        if (c < 27) {
            const float* row = g_xt + ((size_t)(b * N0 + sidx[r])) * CX;
            v = (c < 3) ? (row[c] - ctr[c]) : row[c - 3];
        }
        g[r][c] = v;
    }
    __syncthreads();
    {   // layer1: K=28, O=64
        int og = tid & 15, rg = tid >> 4, o0 = og * 4;
        float acc[2][4];
#pragma unroll
        for (int j = 0; j < 4; j++) { float bb = b0[o0 + j]; acc[0][j] = bb; acc[1][j] = bb; }
        mm4<2>(g_wt + OFF_SA1_0, 64, og, 28, &g[rg * 2][0], 28, acc);
#pragma unroll
        for (int r = 0; r < 2; r++)
#pragma unroll
            for (int j = 0; j < 4; j++) h1s[rg * 2 + r][o0 + j] = fmaxf(acc[r][j], 0.0f);
    }
    __syncthreads();
    {   // layer2: K=64, O=128
        int og = tid & 31, rg = tid >> 5, o0 = og * 4;
        float acc[4][4];
#pragma unroll
        for (int r = 0; r < 4; r++)
#pragma unroll
            for (int j = 0; j < 4; j++) acc[r][j] = b1[o0 + j];
        mm4<4>(g_wt + OFF_SA1_1, 128, og, 64, &h1s[rg * 4][0], 64, acc);
#pragma unroll
        for (int r = 0; r < 4; r++)
#pragma unroll
            for (int j = 0; j < 4; j++) h2s[rg * 4 + r][o0 + j] = fmaxf(acc[r][j], 0.0f);
    }
    __syncthreads();
    {   // layer3: K=128, O=128, fused max over 16 rows
        int o = tid;
        float acc[16];
#pragma unroll
        for (int r = 0; r < 16; r++) acc[r] = 0.0f;
        mmcol<16>(g_wt + OFF_SA1_2, 128, o, 128, &h2s[0][0], 128, acc);
        float m = acc[0];
#pragma unroll
        for (int r = 1; r < 16; r++) m = fmaxf(m, acc[r]);
        g_l1p[(size_t)q * 128 + o] = fmaxf(m + b2[o], 0.0f);
    }
}

// ---------------- SA2: gather + MLP(131->128->256) + max over 32 ----------------
__global__ void __launch_bounds__(256) sa2_kernel(const float* __restrict__ b0,
                                                  const float* __restrict__ b1) {
    __shared__ __align__(16) float g  [32][132];
    __shared__ __align__(16) float h1s[32][128];
    __shared__ int   sidx[32];
    __shared__ float ctr[3];
    int q = blockIdx.x;
    int b = q >> 9;
    int tid = threadIdx.x;
    if (tid < 32) sidx[tid] = g_ball2[q * 32 + tid];
    if (tid >= 32 && tid < 35) ctr[tid - 32] = ((const float*)&g_l2xyz4[q])[tid - 32];
    __syncthreads();
    for (int e = tid; e < 32 * 132; e += 256) {
        int r = e / 132, c = e - r * 132;
        float v = 0.0f;
        if (c < 131) {
            int p = sidx[r];
            if (c < 3) v = ((const float*)&g_l1xyz4[(size_t)b * S1 + p])[c] - ctr[c];
            else       v = g_l1p[((size_t)b * S1 + p) * 128 + (c - 3)];
        }
        g[r][c] = v;
    }
    __syncthreads();
    {   // layer1: K=132, O=128
        int og = tid & 31, rg = tid >> 5, o0 = og * 4;
        float acc[4][4];
#pragma unroll
        for (int r = 0; r < 4; r++)
#pragma unroll
            for (int j = 0; j < 4; j++) acc[r][j] = b0[o0 + j];
        mm4<4>(g_wt + OFF_SA2_0, 128, og, 132, &g[rg * 4][0], 132, acc);
#pragma unroll
        for (int r = 0; r < 4; r++)
#pragma unroll
            for (int j = 0; j < 4; j++) h1s[rg * 4 + r][o0 + j] = fmaxf(acc[r][j], 0.0f);
    }
    __syncthreads();
    {   // layer2: K=128, O=256, fused max over 32 rows
        int o = tid;
        float acc[32];
#pragma unroll
        for (int r = 0; r < 32; r++) acc[r] = 0.0f;
        mmcol<32>(g_wt + OFF_SA2_1, 256, o, 128, &h1s[0][0], 128, acc);
        float m = acc[0];
#pragma unroll
        for (int r = 1; r < 32; r++) m = fmaxf(m, acc[r]);
        g_l2p[(size_t)q * 256 + o] = fmaxf(m + b1[o], 0.0f);
    }
}

// ---------------- FP2: interp(l2->l1) + concat + MLP(384->256->256) ----------------
__global__ void __launch_bounds__(256) fp2_kernel(const float* __restrict__ b0,
                                                  const float* __restrict__ b1) {
    __shared__ __align__(16) float feat[16][384];
    __shared__ __align__(16) float h1s [16][256];
    __shared__ int   nni[16][3];
    __shared__ float nnw[16][3];
    int row0 = blockIdx.x * 16;
    int b = row0 >> 10;
    int tid = threadIdx.x;
    if (tid < 48)                   nni[tid / 3][tid % 3] = g_nn2i[(size_t)row0 * 3 + tid];
    else if (tid < 96) { int t = tid - 48; nnw[t / 3][t % 3] = g_nn2w[(size_t)row0 * 3 + t]; }
    for (int e = tid; e < 16 * 128; e += 256) {
        int r = e >> 7, c = e & 127;
        feat[r][c] = g_l1p[((size_t)row0 + r) * 128 + c];
    }
    __syncthreads();
    {
        const float* p2 = g_l2p + (size_t)b * S2 * 256;
        int c = tid;
#pragma unroll 4
        for (int r = 0; r < 16; r++) {
            float v = p2[(size_t)nni[r][0] * 256 + c] * nnw[r][0];
            v += p2[(size_t)nni[r][1] * 256 + c] * nnw[r][1];
            v += p2[(size_t)nni[r][2] * 256 + c] * nnw[r][2];
            feat[r][128 + c] = v;
        }
    }
    __syncthreads();
    int og = tid & 63, rg = tid >> 6, o0 = og * 4;
    {   // layer1: K=384, O=256
        float acc[4][4];
#pragma unroll
        for (int r = 0; r < 4; r++)
#pragma unroll
            for (int j = 0; j < 4; j++) acc[r][j] = b0[o0 + j];
        mm4<4>(g_wt + OFF_FP2_0, 256, og, 384, &feat[rg * 4][0], 384, acc);
#pragma unroll
        for (int r = 0; r < 4; r++)
#pragma unroll
            for (int j = 0; j < 4; j++) h1s[rg * 4 + r][o0 + j] = fmaxf(acc[r][j], 0.0f);
    }
    __syncthreads();
    {   // layer2: K=256, O=256
        float acc[4][4];
#pragma unroll
        for (int r = 0; r < 4; r++)
#pragma unroll
            for (int j = 0; j < 4; j++) acc[r][j] = b1[o0 + j];
        mm4<4>(g_wt + OFF_FP2_1, 256, og, 256, &h1s[rg * 4][0], 256, acc);
#pragma unroll
        for (int r = 0; r < 4; r++)
#pragma unroll
            for (int j = 0; j < 4; j++)
                g_l1p2[((size_t)row0 + rg * 4 + r) * 256 + o0 + j] = fmaxf(acc[r][j], 0.0f);
    }
}

// ---------------- FP1: concat(l0_xyz, x, interp) + MLP(283->256->256) -> out ----------------
constexpr int FP1_ROWS = 32;
constexpr int FP1_FEAT = FP1_ROWS * 284;
constexpr int FP1_SMEM = (FP1_FEAT + FP1_ROWS * 256) * 4;

__global__ void __launch_bounds__(256) fp1_kernel(const float* __restrict__ b0,
                                                  const float* __restrict__ b1,
                                                  float* __restrict__ out) {
    extern __shared__ float sdyn[];
    float* feat = sdyn;                 // [32][284]
    float* h1s  = sdyn + FP1_FEAT;      // [32][256]
    __shared__ int   nni[FP1_ROWS][3];
    __shared__ float nnw[FP1_ROWS][3];
    int row0 = blockIdx.x * FP1_ROWS;
    int b = row0 >> 13;
    int tid = threadIdx.x;
    if (tid < 96)                    nni[tid / 3][tid % 3] = g_nn1i[(size_t)row0 * 3 + tid];
    else if (tid < 192) { int t = tid - 96; nnw[t / 3][t % 3] = g_nn1w[(size_t)row0 * 3 + t]; }
    for (int e = tid; e < FP1_ROWS * 27; e += 256) {
        int r = e / 27, c = e - r * 27;
        const float* row = g_xt + (size_t)(row0 + r) * CX;
        feat[r * 284 + c] = (c < 3) ? row[c] : row[c - 3];
    }
    if (tid < FP1_ROWS) feat[tid * 284 + 283] = 0.0f;
    __syncthreads();
    {
        const float* p1 = g_l1p2 + (size_t)b * S1 * 256;
        int c = tid;
#pragma unroll 4
        for (int r = 0; r < FP1_ROWS; r++) {
            float v = p1[(size_t)nni[r][0] * 256 + c] * nnw[r][0];
            v += p1[(size_t)nni[r][1] * 256 + c] * nnw[r][1];
            v += p1[(size_t)nni[r][2] * 256 + c] * nnw[r][2];
            feat[r * 284 + 27 + c] = v;
        }
    }
    __syncthreads();
    int og = tid & 63, rg = tid >> 6, o0 = og * 4;   // 4 row-groups x 8 rows
    {   // layer1: K=284, O=256
        float acc[8][4];
#pragma unroll
        for (int r = 0; r < 8; r++)
#pragma unroll
            for (int j = 0; j < 4; j++) acc[r][j] = b0[o0 + j];
        mm4<8>(g_wt + OFF_FP1_0, 256, og, 284, feat + rg * 8 * 284, 284, acc);
#pragma unroll
        for (int r = 0; r < 8; r++)
#pragma unroll
            for (int j = 0; j < 4; j++)
                h1s[(rg * 8 + r) * 256 + o0 + j] = fmaxf(acc[r][j], 0.0f);
    }
    __syncthreads();
    {   // layer2: K=256, O=256
        float acc[8][4];
#pragma unroll
        for (int r = 0; r < 8; r++)
#pragma unroll
            for (int j = 0; j < 4; j++) acc[r][j] = b1[o0 + j];
        mm4<8>(g_wt + OFF_FP1_1, 256, og, 256, h1s + rg * 8 * 256, 256, acc);
#pragma unroll
        for (int r = 0; r < 8; r++)
#pragma unroll
            for (int j = 0; j < 4; j++)
                out[((size_t)row0 + rg * 8 + r) * 256 + o0 + j] = fmaxf(acc[r][j], 0.0f);
    }
}

// ---------------- launch ----------------
extern "C" void kernel_launch(void* const* d_in, const int* in_sizes, int n_in,
                              void* d_out, int out_size) {
    const float* xyz = (const float*)d_in[0];
    const float* sa1_b0 = (const float*)d_in[2];
    const float* sa1_b1 = (const float*)d_in[4];
    const float* sa1_b2 = (const float*)d_in[6];
    const float* sa2_b0 = (const float*)d_in[8];
    const float* sa2_b1 = (const float*)d_in[10];
    const float* fp2_b0 = (const float*)d_in[12];
    const float* fp2_b1 = (const float*)d_in[14];
    const float* fp1_b0 = (const float*)d_in[16];
    const float* fp1_b1 = (const float*)d_in[18];
    float* out = (float*)d_out;

    const float r2_1 = (float)(0.035 * 0.035);
    const float r2_2 = (float)(0.0176 * 0.0176);

    transpose_x_kernel<<<(B * CX * N0 + 255) / 256, 256>>>(xyz);

    WT9 w;
    const int offs[9]  = { OFF_SA1_0, OFF_SA1_1, OFF_SA1_2, OFF_SA2_0, OFF_SA2_1,
                           OFF_FP2_0, OFF_FP2_1, OFF_FP1_0, OFF_FP1_1 };
    const int Os[9]    = { 64, 128, 128, 128, 256, 256, 256, 256, 256 };
    const int Ks[9]    = { 27, 64, 128, 131, 128, 384, 256, 283, 256 };
    const int Kpads[9] = { 28, 64, 128, 132, 128, 384, 256, 284, 256 };
    const int widx[9]  = { 1, 3, 5, 7, 9, 11, 13, 15, 17 };
    int total = 0;
    for (int i = 0; i < 9; i++) {
        w.W[i] = (const float*)d_in[widx[i]];
        w.off[i] = offs[i]; w.O[i] = Os[i]; w.K[i] = Ks[i]; w.Kpad[i] = Kpads[i];
        total += Kpads[i] * Os[i];
    }
    transpose_w9_kernel<<<(total + 255) / 256, 256>>>(w);

    float4* l0 = nullptr; float4* l1 = nullptr; float4* l2 = nullptr;
    cudaGetSymbolAddress((void**)&l0, g_l0xyz4);
    cudaGetSymbolAddress((void**)&l1, g_l1xyz4);
    cudaGetSymbolAddress((void**)&l2, g_l2xyz4);
    int* ball1 = nullptr; cudaGetSymbolAddress((void**)&ball1, g_ball1);
    int* ball2 = nullptr; cudaGetSymbolAddress((void**)&ball2, g_ball2);
    int* nn2i = nullptr; cudaGetSymbolAddress((void**)&nn2i, g_nn2i);
    float* nn2w = nullptr; cudaGetSymbolAddress((void**)&nn2w, g_nn2w);
    int* nn1i = nullptr; cudaGetSymbolAddress((void**)&nn1i, g_nn1i);
    float* nn1w = nullptr; cudaGetSymbolAddress((void**)&nn1w, g_nn1w);

    // SA1
    fps_kernel<8, N0, S1><<<B, 1024>>>(l0, l1);
    ball_kernel<<<(B * S1 * 32 + 255) / 256, 256>>>(l1, l0, N0, S1, r2_1, K1, ball1, B * S1);
    sa1_kernel<<<B * S1, 128>>>(sa1_b0, sa1_b1, sa1_b2);

    // SA2
    fps_kernel<1, S1, S2><<<B, 1024>>>(l1, l2);
    ball_kernel<<<(B * S2 * 32 + 255) / 256, 256>>>(l2, l1, S1, S2, r2_2, K2, ball2, B * S2);
    sa2_kernel<<<B * S2, 256>>>(sa2_b0, sa2_b1);

    // FP2
    nn3_kernel<<<(B * S1 * 32 + 255) / 256, 256>>>(l1, l2, S2, S1, nn2i, nn2w, B * S1);
    fp2_kernel<<<B * S1 / 16, 256>>>(fp2_b0, fp2_b1);

    // FP1
    nn3_kernel<<<(B * N0 * 32 + 255) / 256, 256>>>(l0, l1, S1, N0, nn1i, nn1w, B * N0);
    cudaFuncSetAttribute(fp1_kernel, cudaFuncAttributeMaxDynamicSharedMemorySize, FP1_SMEM);
    fp1_kernel<<<B * N0 / FP1_ROWS, 256, FP1_SMEM>>>(fp1_b0, fp1_b1, out);
}

// round 6
// speedup vs baseline: 1.6225x; 1.0395x over previous
#include <cuda_runtime.h>
#include <cstdint>
#include <cstddef>
#include <float.h>

// ---------------- problem constants ----------------
constexpr int B   = 8;
constexpr int N0  = 8192;
constexpr int CX  = 24;
constexpr int S1  = 1024, K1 = 16;
constexpr int S2  = 512,  K2 = 32;

// ---------------- scratch ----------------
__device__ float  g_xt    [B * N0 * CX];
__device__ float4 g_l0xyz4[B * N0];
__device__ float4 g_l1xyz4[B * S1];
__device__ float4 g_l2xyz4[B * S2];
__device__ int    g_ball1 [B * S1 * K1];
__device__ float  g_l1p   [B * S1 * 128];
__device__ int    g_ball2 [B * S2 * K2];
__device__ float  g_l2p   [B * S2 * 256];
__device__ int    g_nn2i  [B * S1 * 3];
__device__ float  g_nn2w  [B * S1 * 3];
__device__ float  g_l1p2  [B * S1 * 256];
__device__ int    g_nn1i  [B * N0 * 3];
__device__ float  g_nn1w  [B * N0 * 3];
__device__ float  g_wt    [378112];

constexpr int OFF_SA1_0 = 0;        // 28 x 64
constexpr int OFF_SA1_1 = 1792;     // 64 x 128
constexpr int OFF_SA1_2 = 9984;     // 128 x 128
constexpr int OFF_SA2_0 = 26368;    // 132 x 128
constexpr int OFF_SA2_1 = 43264;    // 128 x 256
constexpr int OFF_FP2_0 = 76032;    // 384 x 256
constexpr int OFF_FP2_1 = 174336;   // 256 x 256
constexpr int OFF_FP1_0 = 239872;   // 284 x 256
constexpr int OFF_FP1_1 = 312576;   // 256 x 256
constexpr int TOTAL_W   = 378112;

// ---------------- numeric helpers (pinned op order) ----------------
__device__ __forceinline__ float sumsq3(float x, float y, float z) {
    return fmaf(z, z, fmaf(y, y, __fmul_rn(x, x)));
}
// sc, sp precomputed with sumsq3 (bit-identical to fresh computation)
__device__ __forceinline__ float sqdist_pre(float sc, float cx, float cy, float cz,
                                            float px, float py, float pz, float sp) {
    float dot = fmaf(cz, pz, fmaf(cy, py, __fmul_rn(cx, px)));
    return __fsub_rn(__fadd_rn(sc, sp), __fmul_rn(2.0f, dot));
}
__device__ __forceinline__ void top3_insert(float d, int p,
                                            float& D0, float& D1, float& D2,
                                            int& I0, int& I1, int& I2) {
    if (d < D2 || (d == D2 && p < I2)) {
        if (d < D1 || (d == D1 && p < I1)) {
            D2 = D1; I2 = I1;
            if (d < D0 || (d == D0 && p < I0)) { D1 = D0; I1 = I0; D0 = d; I0 = p; }
            else                               { D1 = d;  I1 = p; }
        } else { D2 = d; I2 = p; }
    }
}
// warp argmax of non-negative float value with min-index tie-break (exact).
__device__ __forceinline__ void warp_argmax(float& v, int& i) {
    unsigned vb = __float_as_uint(v);
    unsigned m  = __reduce_max_sync(0xffffffffu, vb);
    unsigned ci = (vb == m) ? (unsigned)i : 0xffffffffu;
    unsigned bi = __reduce_min_sync(0xffffffffu, ci);
    v = __uint_as_float(m);
    i = (int)bi;
}

// acc[r][j] += sum_k in[r][k] * Wt[k][og*4+j]
template <int NR>
__device__ __forceinline__ void mm4(const float* __restrict__ wt, int O, int og, int KP,
                                    const float* __restrict__ in0, int ld, float (&acc)[NR][4]) {
    const float4* wt4 = reinterpret_cast<const float4*>(wt);
    const int OV4 = O >> 2;
#pragma unroll 2
    for (int k = 0; k < KP; k += 4) {
        float4 wa = wt4[(k + 0) * OV4 + og];
        float4 wb = wt4[(k + 1) * OV4 + og];
        float4 wc = wt4[(k + 2) * OV4 + og];
        float4 wd = wt4[(k + 3) * OV4 + og];
#pragma unroll
        for (int r = 0; r < NR; r++) {
            const float4 gv = *reinterpret_cast<const float4*>(in0 + r * ld + k);
            acc[r][0] += gv.x * wa.x; acc[r][0] += gv.y * wb.x; acc[r][0] += gv.z * wc.x; acc[r][0] += gv.w * wd.x;
            acc[r][1] += gv.x * wa.y; acc[r][1] += gv.y * wb.y; acc[r][1] += gv.z * wc.y; acc[r][1] += gv.w * wd.y;
            acc[r][2] += gv.x * wa.z; acc[r][2] += gv.y * wb.z; acc[r][2] += gv.z * wc.z; acc[r][2] += gv.w * wd.z;
            acc[r][3] += gv.x * wa.w; acc[r][3] += gv.y * wb.w; acc[r][3] += gv.z * wc.w; acc[r][3] += gv.w * wd.w;
        }
    }
}

// acc[r] += sum_k in[r][k] * Wt[k][o]
template <int NR>
__device__ __forceinline__ void mmcol(const float* __restrict__ wt, int O, int o, int KP,
                                      const float* __restrict__ in0, int ld, float (&acc)[NR]) {
#pragma unroll 2
    for (int k = 0; k < KP; k += 4) {
        float wa = wt[(k + 0) * O + o];
        float wb = wt[(k + 1) * O + o];
        float wc = wt[(k + 2) * O + o];
        float wd = wt[(k + 3) * O + o];
#pragma unroll
        for (int r = 0; r < NR; r++) {
            const float4 gv = *reinterpret_cast<const float4*>(in0 + r * ld + k);
            acc[r] += gv.x * wa; acc[r] += gv.y * wb; acc[r] += gv.z * wc; acc[r] += gv.w * wd;
        }
    }
}

// ---------------- prep: point transpose + |p|^2 + all 9 weight transposes ----------------
struct WT9 {
    const float* W[9];
    int off[9], O[9], K[9], Kpad[9];
};
__global__ void prep_kernel(const float* __restrict__ xyz, WT9 w) {
    int i = blockIdx.x * blockDim.x + threadIdx.x;
    if (i < B * N0) {
        int b = i >> 13, n = i & (N0 - 1);
        const float* src = xyz + (size_t)b * CX * N0 + n;
        float* dst = g_xt + (size_t)i * CX;
        float x = src[0], y = src[(size_t)N0], z = src[(size_t)2 * N0];
#pragma unroll
        for (int c = 0; c < CX; c++) dst[c] = src[(size_t)c * N0];
        g_l0xyz4[i] = make_float4(x, y, z, sumsq3(x, y, z));
        return;
    }
    i -= B * N0;
#pragma unroll
    for (int s = 0; s < 9; s++) {
        int n = w.Kpad[s] * w.O[s];
        if (i < n) {
            int k = i / w.O[s], o = i - k * w.O[s];
            g_wt[w.off[s] + i] = (k < w.K[s]) ? w.W[s][o * w.K[s] + k] : 0.0f;
            return;
        }
        i -= n;
    }
}

// ---------------- FPS body (1 block, 1024 threads, PPT points/thread) ----------------
template <int PPT, int NPTS, int NP>
__device__ __forceinline__ void fps_body(const float4* __restrict__ base,
                                         float4* __restrict__ out4,
                                         int tid, int* s_far, float* s_v, int* s_i) {
    float px[PPT], py[PPT], pz[PPT], dist[PPT];
#pragma unroll
    for (int j = 0; j < PPT; j++) {
        float4 P = base[tid + j * 1024];
        px[j] = P.x; py[j] = P.y; pz[j] = P.z;
        dist[j] = 1e10f;
    }
    if (tid == 0) *s_far = 0;
    __syncthreads();
    for (int it = 0; it < NP; it++) {
        int far = *s_far;
        float4 C = base[far];
        float cx = C.x, cy = C.y, cz = C.z;
        if (tid == 0) out4[it] = make_float4(cx, cy, cz, sumsq3(cx, cy, cz));
        float bv = -1.0f; int bj = 0;
#pragma unroll
        for (int j = 0; j < PPT; j++) {
            float dx = __fsub_rn(px[j], cx);
            float dy = __fsub_rn(py[j], cy);
            float dz = __fsub_rn(pz[j], cz);
            float d = fmaf(dz, dz, fmaf(dy, dy, __fmul_rn(dx, dx)));
            float nd = fminf(dist[j], d);
            dist[j] = nd;
            if (nd > bv) { bv = nd; bj = j; }
        }
        int bi = tid + bj * 1024;
        warp_argmax(bv, bi);
        if ((tid & 31) == 0) { s_v[tid >> 5] = bv; s_i[tid >> 5] = bi; }
        __syncthreads();
        if (tid < 32) {
            bv = s_v[tid]; bi = s_i[tid];
            warp_argmax(bv, bi);
            if (tid == 0) *s_far = bi;
        }
        __syncthreads();
    }
}

__global__ void __launch_bounds__(1024) fps8_kernel(const float4* __restrict__ pts4,
                                                    float4* __restrict__ out4) {
    __shared__ int   s_far;
    __shared__ float s_v[32];
    __shared__ int   s_i[32];
    fps_body<8, N0, S1>(pts4 + (size_t)blockIdx.x * N0, out4 + (size_t)blockIdx.x * S1,
                        threadIdx.x, &s_far, s_v, s_i);
}

// ---------------- warp ball-query body ----------------
__device__ __forceinline__ void ball_body(const float4* __restrict__ centers,
                                          const float4* __restrict__ pts4,
                                          int nptsB, int SQ, float r2, int nsample,
                                          int* __restrict__ out, int gw, int lane,
                                          int* __restrict__ buf) {
    int b = gw / SQ;
    float4 C = centers[gw];
    float cx = C.x, cy = C.y, cz = C.z, sc = C.w;
    const float4* pb = pts4 + (size_t)b * nptsB;
    int kept = 0;
    for (int j0 = 0; j0 < nptsB; j0 += 32) {
        int p = j0 + lane;
        float4 P = pb[p];
        float d = sqdist_pre(sc, cx, cy, cz, P.x, P.y, P.z, P.w);
        bool in = !(d > r2);
        unsigned m = __ballot_sync(0xffffffffu, in);
        int rank = kept + __popc(m & ((1u << lane) - 1u));
        if (in && rank < nsample) buf[rank] = p;
        kept += __popc(m);
        if (kept >= nsample) break;
    }
    __syncwarp();
    int first = buf[0];
    for (int i = lane; i < nsample; i += 32)
        out[(size_t)gw * nsample + i] = (i < kept) ? buf[i] : first;
}

// ---------------- warp 3-NN body ----------------
__device__ __forceinline__ void nn3_body(const float4* __restrict__ qpts4,
                                         const float4* __restrict__ pts4,
                                         int nptsB, int SQ,
                                         int* __restrict__ oi, float* __restrict__ ow,
                                         int gw, int lane) {
    int b = gw / SQ;
    float4 Q = qpts4[gw];
    float cx = Q.x, cy = Q.y, cz = Q.z, sc = Q.w;
    const float4* pb = pts4 + (size_t)b * nptsB;
    float D0 = FLT_MAX, D1 = FLT_MAX, D2 = FLT_MAX;
    int   I0 = 0x7fffffff, I1 = 0x7fffffff, I2 = 0x7fffffff;
    for (int p = lane; p < nptsB; p += 32) {
        float4 P = pb[p];
        float d = sqdist_pre(sc, cx, cy, cz, P.x, P.y, P.z, P.w);
        top3_insert(d, p, D0, D1, D2, I0, I1, I2);
    }
    for (int off = 16; off; off >>= 1) {
        float e0 = __shfl_down_sync(0xffffffffu, D0, off);
        float e1 = __shfl_down_sync(0xffffffffu, D1, off);
        float e2 = __shfl_down_sync(0xffffffffu, D2, off);
        int   f0 = __shfl_down_sync(0xffffffffu, I0, off);
        int   f1 = __shfl_down_sync(0xffffffffu, I1, off);
        int   f2 = __shfl_down_sync(0xffffffffu, I2, off);
        top3_insert(e0, f0, D0, D1, D2, I0, I1, I2);
        top3_insert(e1, f1, D0, D1, D2, I0, I1, I2);
        top3_insert(e2, f2, D0, D1, D2, I0, I1, I2);
    }
    if (lane == 0) {
        float r0 = 1.0f / (D0 + 1e-8f);
        float r1 = 1.0f / (D1 + 1e-8f);
        float r2 = 1.0f / (D2 + 1e-8f);
        float s = (r0 + r1) + r2;
        oi[(size_t)gw * 3 + 0] = I0; oi[(size_t)gw * 3 + 1] = I1; oi[(size_t)gw * 3 + 2] = I2;
        ow[(size_t)gw * 3 + 0] = r0 / s; ow[(size_t)gw * 3 + 1] = r1 / s; ow[(size_t)gw * 3 + 2] = r2 / s;
    }
}

// ---------------- M1: fps1 (blocks 0..7) + ball1 (blocks 8..263) ----------------
__global__ void __launch_bounds__(1024) m1_kernel(float r2_1) {
    __shared__ int   sbuf[32][32];
    __shared__ int   s_far;
    __shared__ float s_v[32];
    __shared__ int   s_i[32];
    if (blockIdx.x < B) {
        fps_body<1, S1, S2>(g_l1xyz4 + (size_t)blockIdx.x * S1,
                            g_l2xyz4 + (size_t)blockIdx.x * S2,
                            threadIdx.x, &s_far, s_v, s_i);
    } else {
        int wl = threadIdx.x >> 5, lane = threadIdx.x & 31;
        int gw = (blockIdx.x - B) * 32 + wl;            // 0..8191
        ball_body(g_l1xyz4, g_l0xyz4, N0, S1, r2_1, K1, g_ball1, gw, lane, &sbuf[wl][0]);
    }
}

// ---------------- M2: sa1 + ball2 + nn2 + nn1 (128 threads) ----------------
constexpr int M2_SA1   = 8192;
constexpr int M2_BALL2 = 1024;   // 4096 queries / 4 warps
constexpr int M2_NN2   = 2048;   // 8192 queries / 4 warps
constexpr int M2_NN1   = 16384;  // 65536 queries / 4 warps
constexpr int M2_GRID  = M2_SA1 + M2_BALL2 + M2_NN2 + M2_NN1;

__global__ void __launch_bounds__(128) m2_kernel(const float* __restrict__ b0,
                                                 const float* __restrict__ b1,
                                                 const float* __restrict__ b2,
                                                 float r2_2) {
    __shared__ __align__(16) float g  [16][28];
    __shared__ __align__(16) float h1s[16][64];
    __shared__ __align__(16) float h2s[16][128];
    __shared__ int   sidx[16];
    __shared__ float ctr[3];
    __shared__ int   sbuf[4][32];
    int bid = blockIdx.x;
    int tid = threadIdx.x;
    int wl = tid >> 5, lane = tid & 31;

    if (bid >= M2_SA1) {
        int r = bid - M2_SA1;
        if (r < M2_BALL2) {
            int gw = r * 4 + wl;                         // 0..4095
            ball_body(g_l2xyz4, g_l1xyz4, S1, S2, r2_2, K2, g_ball2, gw, lane, &sbuf[wl][0]);
        } else if (r < M2_BALL2 + M2_NN2) {
            int gw = (r - M2_BALL2) * 4 + wl;            // 0..8191
            nn3_body(g_l1xyz4, g_l2xyz4, S2, S1, g_nn2i, g_nn2w, gw, lane);
        } else {
            int gw = (r - M2_BALL2 - M2_NN2) * 4 + wl;   // 0..65535
            nn3_body(g_l0xyz4, g_l1xyz4, S1, N0, g_nn1i, g_nn1w, gw, lane);
        }
        return;
    }

    // ---- sa1 ----
    int q = bid;
    int b = q >> 10;
    if (tid < 16) sidx[tid] = g_ball1[q * 16 + tid];
    if (tid >= 16 && tid < 19) ctr[tid - 16] = ((const float*)&g_l1xyz4[q])[tid - 16];
    __syncthreads();
    for (int e = tid; e < 16 * 28; e += 128) {
        int r = e / 28, c = e - r * 28;
        float v = 0.0f;
        if (c < 27) {
            const float* row = g_xt + ((size_t)(b * N0 + sidx[r])) * CX;
            v = (c < 3) ? (row[c] - ctr[c]) : row[c - 3];
        }
        g[r][c] = v;
    }
    __syncthreads();
    {   // layer1: K=28, O=64
        int og = tid & 15, rg = tid >> 4, o0 = og * 4;
        float acc[2][4];
#pragma unroll
        for (int j = 0; j < 4; j++) { float bb = b0[o0 + j]; acc[0][j] = bb; acc[1][j] = bb; }
        mm4<2>(g_wt + OFF_SA1_0, 64, og, 28, &g[rg * 2][0], 28, acc);
#pragma unroll
        for (int r = 0; r < 2; r++)
#pragma unroll
            for (int j = 0; j < 4; j++) h1s[rg * 2 + r][o0 + j] = fmaxf(acc[r][j], 0.0f);
    }
    __syncthreads();
    {   // layer2: K=64, O=128
        int og = tid & 31, rg = tid >> 5, o0 = og * 4;
        float acc[4][4];
#pragma unroll
        for (int r = 0; r < 4; r++)
#pragma unroll
            for (int j = 0; j < 4; j++) acc[r][j] = b1[o0 + j];
        mm4<4>(g_wt + OFF_SA1_1, 128, og, 64, &h1s[rg * 4][0], 64, acc);
#pragma unroll
        for (int r = 0; r < 4; r++)
#pragma unroll
            for (int j = 0; j < 4; j++) h2s[rg * 4 + r][o0 + j] = fmaxf(acc[r][j], 0.0f);
    }
    __syncthreads();
    {   // layer3: K=128, O=128, fused max over 16 rows
        int o = tid;
        float acc[16];
#pragma unroll
        for (int r = 0; r < 16; r++) acc[r] = 0.0f;
        mmcol<16>(g_wt + OFF_SA1_2, 128, o, 128, &h2s[0][0], 128, acc);
        float m = acc[0];
#pragma unroll
        for (int r = 1; r < 16; r++) m = fmaxf(m, acc[r]);
        g_l1p[(size_t)q * 128 + o] = fmaxf(m + b2[o], 0.0f);
    }
}

// ---------------- SA2: gather + MLP(131->128->256) + max over 32 ----------------
__global__ void __launch_bounds__(256) sa2_kernel(const float* __restrict__ b0,
                                                  const float* __restrict__ b1) {
    __shared__ __align__(16) float g  [32][132];
    __shared__ __align__(16) float h1s[32][128];
    __shared__ int   sidx[32];
    __shared__ float ctr[3];
    int q = blockIdx.x;
    int b = q >> 9;
    int tid = threadIdx.x;
    if (tid < 32) sidx[tid] = g_ball2[q * 32 + tid];
    if (tid >= 32 && tid < 35) ctr[tid - 32] = ((const float*)&g_l2xyz4[q])[tid - 32];
    __syncthreads();
    for (int e = tid; e < 32 * 132; e += 256) {
        int r = e / 132, c = e - r * 132;
        float v = 0.0f;
        if (c < 131) {
            int p = sidx[r];
            if (c < 3) v = ((const float*)&g_l1xyz4[(size_t)b * S1 + p])[c] - ctr[c];
            else       v = g_l1p[((size_t)b * S1 + p) * 128 + (c - 3)];
        }
        g[r][c] = v;
    }
    __syncthreads();
    {   // layer1: K=132, O=128
        int og = tid & 31, rg = tid >> 5, o0 = og * 4;
        float acc[4][4];
#pragma unroll
        for (int r = 0; r < 4; r++)
#pragma unroll
            for (int j = 0; j < 4; j++) acc[r][j] = b0[o0 + j];
        mm4<4>(g_wt + OFF_SA2_0, 128, og, 132, &g[rg * 4][0], 132, acc);
#pragma unroll
        for (int r = 0; r < 4; r++)
#pragma unroll
            for (int j = 0; j < 4; j++) h1s[rg * 4 + r][o0 + j] = fmaxf(acc[r][j], 0.0f);
    }
    __syncthreads();
    {   // layer2: K=128, O=256, fused max over 32 rows
        int o = tid;
        float acc[32];
#pragma unroll
        for (int r = 0; r < 32; r++) acc[r] = 0.0f;
        mmcol<32>(g_wt + OFF_SA2_1, 256, o, 128, &h1s[0][0], 128, acc);
        float m = acc[0];
#pragma unroll
        for (int r = 1; r < 32; r++) m = fmaxf(m, acc[r]);
        g_l2p[(size_t)q * 256 + o] = fmaxf(m + b1[o], 0.0f);
    }
}

// ---------------- FP2: interp(l2->l1) + concat + MLP(384->256->256) ----------------
__global__ void __launch_bounds__(256) fp2_kernel(const float* __restrict__ b0,
                                                  const float* __restrict__ b1) {
    __shared__ __align__(16) float feat[16][384];
    __shared__ __align__(16) float h1s [16][256];
    __shared__ int   nni[16][3];
    __shared__ float nnw[16][3];
    int row0 = blockIdx.x * 16;
    int b = row0 >> 10;
    int tid = threadIdx.x;
    if (tid < 48)                   nni[tid / 3][tid % 3] = g_nn2i[(size_t)row0 * 3 + tid];
    else if (tid < 96) { int t = tid - 48; nnw[t / 3][t % 3] = g_nn2w[(size_t)row0 * 3 + t]; }
    for (int e = tid; e < 16 * 128; e += 256) {
        int r = e >> 7, c = e & 127;
        feat[r][c] = g_l1p[((size_t)row0 + r) * 128 + c];
    }
    __syncthreads();
    {
        const float* p2 = g_l2p + (size_t)b * S2 * 256;
        int c = tid;
#pragma unroll 4
        for (int r = 0; r < 16; r++) {
            float v = p2[(size_t)nni[r][0] * 256 + c] * nnw[r][0];
            v += p2[(size_t)nni[r][1] * 256 + c] * nnw[r][1];
            v += p2[(size_t)nni[r][2] * 256 + c] * nnw[r][2];
            feat[r][128 + c] = v;
        }
    }
    __syncthreads();
    int og = tid & 63, rg = tid >> 6, o0 = og * 4;
    {   // layer1: K=384, O=256
        float acc[4][4];
#pragma unroll
        for (int r = 0; r < 4; r++)
#pragma unroll
            for (int j = 0; j < 4; j++) acc[r][j] = b0[o0 + j];
        mm4<4>(g_wt + OFF_FP2_0, 256, og, 384, &feat[rg * 4][0], 384, acc);
#pragma unroll
        for (int r = 0; r < 4; r++)
#pragma unroll
            for (int j = 0; j < 4; j++) h1s[rg * 4 + r][o0 + j] = fmaxf(acc[r][j], 0.0f);
    }
    __syncthreads();
    {   // layer2: K=256, O=256
        float acc[4][4];
#pragma unroll
        for (int r = 0; r < 4; r++)
#pragma unroll
            for (int j = 0; j < 4; j++) acc[r][j] = b1[o0 + j];
        mm4<4>(g_wt + OFF_FP2_1, 256, og, 256, &h1s[rg * 4][0], 256, acc);
#pragma unroll
        for (int r = 0; r < 4; r++)
#pragma unroll
            for (int j = 0; j < 4; j++)
                g_l1p2[((size_t)row0 + rg * 4 + r) * 256 + o0 + j] = fmaxf(acc[r][j], 0.0f);
    }
}

// ---------------- FP1: concat(l0_xyz, x, interp) + MLP(283->256->256) -> out ----------------
constexpr int FP1_ROWS = 32;
constexpr int FP1_FEAT = FP1_ROWS * 284;
constexpr int FP1_SMEM = (FP1_FEAT + FP1_ROWS * 256) * 4;

__global__ void __launch_bounds__(256) fp1_kernel(const float* __restrict__ b0,
                                                  const float* __restrict__ b1,
                                                  float* __restrict__ out) {
    extern __shared__ float sdyn[];
    float* feat = sdyn;                 // [32][284]
    float* h1s  = sdyn + FP1_FEAT;      // [32][256]
    __shared__ int   nni[FP1_ROWS][3];
    __shared__ float nnw[FP1_ROWS][3];
    int row0 = blockIdx.x * FP1_ROWS;
    int b = row0 >> 13;
    int tid = threadIdx.x;
    if (tid < 96)                    nni[tid / 3][tid % 3] = g_nn1i[(size_t)row0 * 3 + tid];
    else if (tid < 192) { int t = tid - 96; nnw[t / 3][t % 3] = g_nn1w[(size_t)row0 * 3 + t]; }
    for (int e = tid; e < FP1_ROWS * 27; e += 256) {
        int r = e / 27, c = e - r * 27;
        const float* row = g_xt + (size_t)(row0 + r) * CX;
        feat[r * 284 + c] = (c < 3) ? row[c] : row[c - 3];
    }
    if (tid < FP1_ROWS) feat[tid * 284 + 283] = 0.0f;
    __syncthreads();
    {
        const float* p1 = g_l1p2 + (size_t)b * S1 * 256;
        int c = tid;
#pragma unroll 4
        for (int r = 0; r < FP1_ROWS; r++) {
            float v = p1[(size_t)nni[r][0] * 256 + c] * nnw[r][0];
            v += p1[(size_t)nni[r][1] * 256 + c] * nnw[r][1];
            v += p1[(size_t)nni[r][2] * 256 + c] * nnw[r][2];
            feat[r * 284 + 27 + c] = v;
        }
    }
    __syncthreads();
    int og = tid & 63, rg = tid >> 6, o0 = og * 4;   // 4 row-groups x 8 rows
    {   // layer1: K=284, O=256
        float acc[8][4];
#pragma unroll
        for (int r = 0; r < 8; r++)
#pragma unroll
            for (int j = 0; j < 4; j++) acc[r][j] = b0[o0 + j];
        mm4<8>(g_wt + OFF_FP1_0, 256, og, 284, feat + rg * 8 * 284, 284, acc);
#pragma unroll
        for (int r = 0; r < 8; r++)
#pragma unroll
            for (int j = 0; j < 4; j++)
                h1s[(rg * 8 + r) * 256 + o0 + j] = fmaxf(acc[r][j], 0.0f);
    }
    __syncthreads();
    {   // layer2: K=256, O=256
        float acc[8][4];
#pragma unroll
        for (int r = 0; r < 8; r++)
#pragma unroll
            for (int j = 0; j < 4; j++) acc[r][j] = b1[o0 + j];
        mm4<8>(g_wt + OFF_FP1_1, 256, og, 256, h1s + rg * 8 * 256, 256, acc);
#pragma unroll
        for (int r = 0; r < 8; r++)
#pragma unroll
            for (int j = 0; j < 4; j++)
                out[((size_t)row0 + rg * 8 + r) * 256 + o0 + j] = fmaxf(acc[r][j], 0.0f);
    }
}

// ---------------- launch ----------------
extern "C" void kernel_launch(void* const* d_in, const int* in_sizes, int n_in,
                              void* d_out, int out_size) {
    const float* xyz = (const float*)d_in[0];
    const float* sa1_b0 = (const float*)d_in[2];
    const float* sa1_b1 = (const float*)d_in[4];
    const float* sa1_b2 = (const float*)d_in[6];
    const float* sa2_b0 = (const float*)d_in[8];
    const float* sa2_b1 = (const float*)d_in[10];
    const float* fp2_b0 = (const float*)d_in[12];
    const float* fp2_b1 = (const float*)d_in[14];
    const float* fp1_b0 = (const float*)d_in[16];
    const float* fp1_b1 = (const float*)d_in[18];
    float* out = (float*)d_out;

    const float r2_1 = (float)(0.035 * 0.035);
    const float r2_2 = (float)(0.0176 * 0.0176);

    WT9 w;
    const int offs[9]  = { OFF_SA1_0, OFF_SA1_1, OFF_SA1_2, OFF_SA2_0, OFF_SA2_1,
                           OFF_FP2_0, OFF_FP2_1, OFF_FP1_0, OFF_FP1_1 };
    const int Os[9]    = { 64, 128, 128, 128, 256, 256, 256, 256, 256 };
    const int Ks[9]    = { 27, 64, 128, 131, 128, 384, 256, 283, 256 };
    const int Kpads[9] = { 28, 64, 128, 132, 128, 384, 256, 284, 256 };
    const int widx[9]  = { 1, 3, 5, 7, 9, 11, 13, 15, 17 };
    for (int i = 0; i < 9; i++) {
        w.W[i] = (const float*)d_in[widx[i]];
        w.off[i] = offs[i]; w.O[i] = Os[i]; w.K[i] = Ks[i]; w.Kpad[i] = Kpads[i];
    }
    prep_kernel<<<(B * N0 + TOTAL_W + 255) / 256, 256>>>(xyz, w);

    float4* l0 = nullptr; float4* l1 = nullptr;
    cudaGetSymbolAddress((void**)&l0, g_l0xyz4);
    cudaGetSymbolAddress((void**)&l1, g_l1xyz4);

    fps8_kernel<<<B, 1024>>>(l0, l1);
    m1_kernel<<<B + 256, 1024>>>(r2_1);
    m2_kernel<<<M2_GRID, 128>>>(sa1_b0, sa1_b1, sa1_b2, r2_2);
    sa2_kernel<<<B * S2, 256>>>(sa2_b0, sa2_b1);
    fp2_kernel<<<B * S1 / 16, 256>>>(fp2_b0, fp2_b1);
    cudaFuncSetAttribute(fp1_kernel, cudaFuncAttributeMaxDynamicSharedMemorySize, FP1_SMEM);
    fp1_kernel<<<B * N0 / FP1_ROWS, 256, FP1_SMEM>>>(fp1_b0, fp1_b1, out);
}